// round 9
// baseline (speedup 1.0000x reference)
#include <cuda_runtime.h>

// LengthRegulator: out[b,t,:] = x[b, tok(b,t), :] where tok = searchsorted(cumsum(dur), t, 'right')
// Static shapes: B=16, L=512, D=512, T_MAX=4096. Output fp32 [B, T, D].

constexpr int B = 16;
constexpr int L = 512;
constexpr int D = 512;          // 512 floats = 128 float4 per row
constexpr int T = 4096;
constexpr int D4 = D / 4;       // 128 float4 per row

// Scratch token indices: tok[b*T + t], -1 => zero-pad frame. 256 KB device global (no alloc).
__device__ int g_tok[B * T];

// Kernel A: per-batch inclusive scan of durations + binary search per output frame.
__global__ void scan_search_kernel(const int* __restrict__ dur) {
    __shared__ int s[L];
    const int b = blockIdx.x;
    const int tid = threadIdx.x;

    s[tid] = dur[b * L + tid];
    __syncthreads();

    #pragma unroll
    for (int off = 1; off < L; off <<= 1) {
        int v = (tid >= off) ? s[tid - off] : 0;
        __syncthreads();
        s[tid] += v;
        __syncthreads();
    }
    const int total = s[L - 1];

    #pragma unroll
    for (int t = tid; t < T; t += L) {
        int tok;
        if (t >= total) {
            tok = -1;
        } else {
            int lo = 0, hi = L;
            while (lo < hi) {                 // full-convergence upper_bound
                int mid = (lo + hi) >> 1;
                if (s[mid] <= t) lo = mid + 1; else hi = mid;
            }
            tok = lo < (L - 1) ? lo : (L - 1);
        }
        g_tok[b * T + t] = tok;
    }
}

// Kernel B: one warp per 4 CONSECUTIVE frames. Durations avg 3.5, so consecutive
// frames usually share a token: reload the 2KB source row only when tok changes.
// All LDG/STG.128 warp-strided & fully coalesced (32 contiguous float4 = 512 B).
__global__ void gather_kernel(const float4* __restrict__ x4, float4* __restrict__ out4) {
    const int wid  = (blockIdx.x * blockDim.x + threadIdx.x) >> 5;  // 16384 warps
    const int lane = threadIdx.x & 31;
    const int fr0  = wid << 2;             // first of 4 consecutive frames (4 | T, so b uniform)
    const int b    = fr0 >> 12;            // / T

    // 4 toks in one broadcast 16B load (g_tok 16B-aligned, fr0 multiple of 4)
    const int4 tokv = *reinterpret_cast<const int4*>(&g_tok[fr0]);
    const int toks[4] = {tokv.x, tokv.y, tokv.z, tokv.w};

    float4 v0, v1, v2, v3;
    int cur = -2;                          // tok currently held in registers (-2 = none)
    const float4* xb = x4 + b * L * D4 + lane;

    #pragma unroll
    for (int f = 0; f < 4; ++f) {
        const int tok = toks[f];
        if (tok >= 0) {
            if (tok != cur) {
                const float4* src = xb + tok * D4;
                v0 = __ldg(src +  0);
                v1 = __ldg(src + 32);
                v2 = __ldg(src + 64);
                v3 = __ldg(src + 96);
                cur = tok;
            }
        } else if (cur != -1) {
            v0 = v1 = v2 = v3 = make_float4(0.f, 0.f, 0.f, 0.f);
            cur = -1;                      // zeros cached; any later tok>=0 forces reload
        }
        float4* dst = out4 + (fr0 + f) * D4 + lane;
        __stcs(dst +  0, v0);
        __stcs(dst + 32, v1);
        __stcs(dst + 64, v2);
        __stcs(dst + 96, v3);
    }
}

extern "C" void kernel_launch(void* const* d_in, const int* in_sizes, int n_in,
                              void* d_out, int out_size) {
    const float* x   = (const float*)d_in[0];
    const int*   dur = (const int*)d_in[1];
    // d_in[2] = mel_max_length (static 4096, baked into constants)

    scan_search_kernel<<<B, L>>>(dur);

    const int total_threads = (B * T / 4) * 32;   // one warp per 4 frames = 524288 threads
    const int threads = 256;
    gather_kernel<<<total_threads / threads, threads>>>((const float4*)x, (float4*)d_out);

    (void)in_sizes; (void)n_in; (void)out_size;
}